// round 12
// baseline (speedup 1.0000x reference)
#include <cuda_runtime.h>
#include <cuda_fp16.h>
#include <cstdint>

#define BZ 32
#define CH 64
#define HH 128
#define WW 128
#define RROWS 8          // output rows per CTA
#define HW (HH * WW)
#define MPW 136          // words per c2-row of Mp: MPW%32==8 -> GEMM reads conflict-free
#define MPSLOT (32 * MPW)        // 4352 words per row-slot
#define WP_STRIDE 33     // words per o-row of packed weights (aliased into ring)
#define ZSL 68           // words per o-row of a z ring slot (64 px-pairs + 4 pad)
#define RINGSLOT (64 * ZSL)      // 4352 words per z row-slot

// dynamic smem layout (bytes):
//   Mp    uint32_t[2][32*136] @ 0       (34816)  fp16x2 x rows, double-buffered (producer-private)
//   ring  uint32_t[4][64*68]  @ 34816   (69632)  fp16x2 z rows, 4-slot ring
//         (Wp aliases ring start during phase 0 only)
//   BiasS float[64]           @ 104448  (256)
#define SMEM_BYTES 104704

// named barriers: 1 = producer-internal (256); FULL(s) = 2+s (512); EMPTY(s) = 6+s (512)
#define NBAR_SYNC(id, cnt)   asm volatile("bar.sync %0, %1;"   :: "r"(id), "r"(cnt) : "memory")
#define NBAR_ARRIVE(id, cnt) asm volatile("bar.arrive %0, %1;" :: "r"(id), "r"(cnt) : "memory")

static __device__ __forceinline__ float2 h2f(uint32_t w) {
    return __half22float2(*reinterpret_cast<__half2*>(&w));
}

__global__ __launch_bounds__(512, 1)
void denoise_fused(const float* __restrict__ x,
                   const float* __restrict__ conv_w,
                   const float* __restrict__ conv_b,
                   float* __restrict__ out) {
    extern __shared__ unsigned char smraw[];
    uint32_t* Mp    = reinterpret_cast<uint32_t*>(smraw);
    uint32_t* ring  = reinterpret_cast<uint32_t*>(smraw + 34816);
    uint32_t* Wp    = ring;                       // alias, dead before ring slot0 first write
    float*    BiasS = reinterpret_cast<float*>(smraw + 104448);

    const int tid  = threadIdx.x;
    const int warp = tid >> 5;
    const int lane = tid & 31;

    const int b  = blockIdx.y;
    const int h0 = blockIdx.x * RROWS;

    // ---------- phase 0: stage weights fp16x2 + bias (all 512 threads) ----------
    for (int i = tid; i < 64 * 32; i += 512) {
        const int o = i >> 5, c2 = i & 31;
        const float2 wv = reinterpret_cast<const float2*>(conv_w)[o * 32 + c2];
        __half2 pk = __floats2half2_rn(wv.x, wv.y);
        Wp[o * WP_STRIDE + c2] = *reinterpret_cast<uint32_t*>(&pk);
    }
    if (tid < 64) BiasS[tid] = conv_b[tid];
    __syncthreads();

    const float* xb = x   + (size_t)b * CH * HW;
    float*       ob = out + (size_t)b * CH * HW;

    if (warp < 8) {
        // ================= PRODUCERS (warps 0-7, tid 0-255) =================
        // GEMM tiling over one full row: 2 M-tiles x 4 N-slices per warp
        const int o0   = (warp & 1) * 32;
        const int nsub = (warp >> 1) * 32;
        const int lq = lane >> 2;   // 0..7
        const int lr = lane & 3;    // 0..3

        uint32_t a[2][4][4];
        #pragma unroll
        for (int mt = 0; mt < 2; mt++) {
            const int ot = o0 + mt * 16;
            #pragma unroll
            for (int kk = 0; kk < 4; kk++) {
                a[mt][kk][0] = Wp[(ot + lq)     * WP_STRIDE + kk * 8 + lr];
                a[mt][kk][1] = Wp[(ot + 8 + lq) * WP_STRIDE + kk * 8 + lr];
                a[mt][kk][2] = Wp[(ot + lq)     * WP_STRIDE + kk * 8 + 4 + lr];
                a[mt][kk][3] = Wp[(ot + 8 + lq) * WP_STRIDE + kk * 8 + 4 + lr];
            }
        }

        // per-thread load coords: channel pair c2p, 16 px starting at pxb
        const int c2p = tid >> 3;           // 0..31
        const int pxb = (tid & 7) * 16;     // 0..112

        // prologue: prefetch row h0-1
        float4 pxa[4], pxc[4];
        if (h0 - 1 >= 0) {
            #pragma unroll
            for (int g = 0; g < 4; g++) {
                pxa[g] = *reinterpret_cast<const float4*>(
                    xb + (size_t)(2 * c2p)     * HW + (h0 - 1) * WW + pxb + 4 * g);
                pxc[g] = *reinterpret_cast<const float4*>(
                    xb + (size_t)(2 * c2p + 1) * HW + (h0 - 1) * WW + pxb + 4 * g);
            }
        }

        #pragma unroll 1
        for (int it = 0; it < RROWS + 2; it++) {
            const int r    = h0 - 1 + it;
            const int slot = (r + 4) & 3;
            const bool valid = (r >= 0) && (r < HH);

            // backpressure: wait until consumers freed this slot's old row
            if (it >= 4) NBAR_SYNC(6 + slot, 512);

            uint32_t* mp = Mp + (it & 1) * MPSLOT;
            if (valid) {
                #pragma unroll
                for (int g = 0; g < 4; g++) {
                    __half2 p0 = __floats2half2_rn(pxa[g].x, pxc[g].x);
                    __half2 p1 = __floats2half2_rn(pxa[g].y, pxc[g].y);
                    __half2 p2 = __floats2half2_rn(pxa[g].z, pxc[g].z);
                    __half2 p3 = __floats2half2_rn(pxa[g].w, pxc[g].w);
                    uint4 pk4 = make_uint4(*reinterpret_cast<uint32_t*>(&p0),
                                           *reinterpret_cast<uint32_t*>(&p1),
                                           *reinterpret_cast<uint32_t*>(&p2),
                                           *reinterpret_cast<uint32_t*>(&p3));
                    *reinterpret_cast<uint4*>(&mp[c2p * MPW + pxb + 4 * g]) = pk4;
                }
            }
            // prefetch row r+1 (latency hidden behind GEMM)
            const int rn = r + 1;
            if (it < RROWS + 1 && rn < HH) {
                #pragma unroll
                for (int g = 0; g < 4; g++) {
                    pxa[g] = *reinterpret_cast<const float4*>(
                        xb + (size_t)(2 * c2p)     * HW + rn * WW + pxb + 4 * g);
                    pxc[g] = *reinterpret_cast<const float4*>(
                        xb + (size_t)(2 * c2p + 1) * HW + rn * WW + pxb + 4 * g);
                }
            }
            NBAR_SYNC(1, 256);   // Mp slot ready for all producer warps

            uint32_t* zs = ring + slot * RINGSLOT;
            if (valid) {
                #pragma unroll
                for (int nt = 0; nt < 4; nt++) {
                    const int n0 = nsub + nt * 8;
                    float ac[2][4];
                    #pragma unroll
                    for (int mt = 0; mt < 2; mt++)
                        ac[mt][0] = ac[mt][1] = ac[mt][2] = ac[mt][3] = 0.f;
                    #pragma unroll
                    for (int kk = 0; kk < 4; kk++) {
                        const uint32_t b0 = mp[(kk * 8 + lr)     * MPW + n0 + lq];
                        const uint32_t b1 = mp[(kk * 8 + 4 + lr) * MPW + n0 + lq];
                        #pragma unroll
                        for (int mt = 0; mt < 2; mt++) {
                            asm volatile(
                                "mma.sync.aligned.m16n8k16.row.col.f32.f16.f16.f32 "
                                "{%0,%1,%2,%3}, {%4,%5,%6,%7}, {%8,%9}, {%0,%1,%2,%3};\n"
                                : "+f"(ac[mt][0]), "+f"(ac[mt][1]),
                                  "+f"(ac[mt][2]), "+f"(ac[mt][3])
                                : "r"(a[mt][kk][0]), "r"(a[mt][kk][1]),
                                  "r"(a[mt][kk][2]), "r"(a[mt][kk][3]),
                                  "r"(b0), "r"(b1));
                        }
                    }
                    #pragma unroll
                    for (int mt = 0; mt < 2; mt++) {
                        const int oA = o0 + mt * 16 + lq;
                        __half2 d01 = __floats2half2_rn(ac[mt][0], ac[mt][1]);
                        __half2 d23 = __floats2half2_rn(ac[mt][2], ac[mt][3]);
                        zs[oA       * ZSL + (n0 >> 1) + lr] = *reinterpret_cast<uint32_t*>(&d01);
                        zs[(oA + 8) * ZSL + (n0 >> 1) + lr] = *reinterpret_cast<uint32_t*>(&d23);
                    }
                }
            } else {
                const uint4 z4 = make_uint4(0u, 0u, 0u, 0u);
                for (int jj = tid; jj < 1088; jj += 256)
                    *reinterpret_cast<uint4*>(&zs[jj * 4]) = z4;
            }
            NBAR_ARRIVE(2 + slot, 512);   // z row r published
        }
    } else {
        // ================= CONSUMERS (warps 8-15, tid 256-511) =================
        const int tid2 = tid & 255;
        int received = 0;   // z rows received so far (row index h0-1+received-1)

        #pragma unroll 1
        for (int oi = 0; oi < RROWS; oi++) {
            const int ro = h0 + oi;
            const int need = oi + 3;      // rows h0-1 .. ro+1
            while (received < need) {
                const int rr = h0 - 1 + received;
                NBAR_SYNC(2 + ((rr + 4) & 3), 512);
                received++;
            }

            const uint32_t* zt  = ring + ((ro - 1 + 4) & 3) * RINGSLOT;
            const uint32_t* zm  = ring + ((ro     + 4) & 3) * RINGSLOT;
            const uint32_t* zb2 = ring + ((ro + 1 + 4) & 3) * RINGSLOT;
            const float invh = (ro == 0 || ro == HH - 1) ? 0.5f : (1.0f / 3.0f);

            #pragma unroll
            for (int it2 = 0; it2 < 4; it2++) {
                const int idx = it2 * 256 + tid2;
                const int o   = idx >> 4;        // out channel 0..63
                const int q4  = idx & 15;        // uint4 group (8 px); == lane & 15
                const int wb  = o * ZSL + q4 * 4;

                // vertical 3-sum of 8 px (LDS.128 x3)
                const uint4 t4 = *reinterpret_cast<const uint4*>(&zt[wb]);
                const uint4 m4 = *reinterpret_cast<const uint4*>(&zm[wb]);
                const uint4 b4 = *reinterpret_cast<const uint4*>(&zb2[wb]);
                float v[8];
                {
                    float2 t, m, bt;
                    t = h2f(t4.x); m = h2f(m4.x); bt = h2f(b4.x);
                    v[0] = t.x + m.x + bt.x;  v[1] = t.y + m.y + bt.y;
                    t = h2f(t4.y); m = h2f(m4.y); bt = h2f(b4.y);
                    v[2] = t.x + m.x + bt.x;  v[3] = t.y + m.y + bt.y;
                    t = h2f(t4.z); m = h2f(m4.z); bt = h2f(b4.z);
                    v[4] = t.x + m.x + bt.x;  v[5] = t.y + m.y + bt.y;
                    t = h2f(t4.w); m = h2f(m4.w); bt = h2f(b4.w);
                    v[6] = t.x + m.x + bt.x;  v[7] = t.y + m.y + bt.y;
                }
                // boundary vertical sums via neighbor lanes (cross-half values
                // at lane 15<->16 discarded by the q4 edge guards)
                const float vls = __shfl_sync(0xffffffffu, v[7], (lane - 1) & 31);
                const float vrs = __shfl_sync(0xffffffffu, v[0], (lane + 1) & 31);
                const float vl = (q4 == 0)  ? 0.f : vls;
                const float vr = (q4 == 15) ? 0.f : vrs;

                // horizontal 3-sum + scale + residual + bias
                const int px0 = q4 * 8;
                const size_t off = (size_t)o * HW + ro * WW + px0;
                const float4 x0 = *reinterpret_cast<const float4*>(xb + off);
                const float4 x1 = *reinterpret_cast<const float4*>(xb + off + 4);
                const float bo = BiasS[o];
                const float iw  = (1.0f / 3.0f) * invh;
                const float iwL = (q4 == 0)  ? 0.5f * invh : iw;
                const float iwR = (q4 == 15) ? 0.5f * invh : iw;

                float4 o0v, o1v;
                o0v.x = x0.x + bo + (vl   + v[0] + v[1]) * iwL;
                o0v.y = x0.y + bo + (v[0] + v[1] + v[2]) * iw;
                o0v.z = x0.z + bo + (v[1] + v[2] + v[3]) * iw;
                o0v.w = x0.w + bo + (v[2] + v[3] + v[4]) * iw;
                o1v.x = x1.x + bo + (v[3] + v[4] + v[5]) * iw;
                o1v.y = x1.y + bo + (v[4] + v[5] + v[6]) * iw;
                o1v.z = x1.z + bo + (v[5] + v[6] + v[7]) * iw;
                o1v.w = x1.w + bo + (v[6] + v[7] + vr  ) * iwR;
                __stcs(reinterpret_cast<float4*>(ob + off), o0v);
                __stcs(reinterpret_cast<float4*>(ob + off + 4), o1v);
            }

            // free z row ro-1 (its slot may be reused by producers)
            NBAR_ARRIVE(6 + ((ro - 1 + 4) & 3), 512);
        }
    }
}

extern "C" void kernel_launch(void* const* d_in, const int* in_sizes, int n_in,
                              void* d_out, int out_size) {
    const float* x      = (const float*)d_in[0];
    const float* conv_w = (const float*)d_in[1];
    const float* conv_b = (const float*)d_in[2];
    float* out = (float*)d_out;

    cudaFuncSetAttribute(denoise_fused,
                         cudaFuncAttributeMaxDynamicSharedMemorySize, SMEM_BYTES);
    dim3 grid(HH / RROWS, BZ);               // 16 x 32 = 512 CTAs
    denoise_fused<<<grid, 512, SMEM_BYTES>>>(x, conv_w, conv_b, out);
}

// round 13
// speedup vs baseline: 1.2715x; 1.2715x over previous
#include <cuda_runtime.h>
#include <cuda_fp16.h>
#include <cstdint>

#define BZ 32
#define CH 64
#define HH 128
#define WW 128
#define RROWS 8          // output rows per CTA (2 per iteration, 4 iterations)
#define HW (HH * WW)
#define MPW 136          // words per c2-row of Mp: MPW%32==8 -> GEMM reads conflict-free
#define MPSLOT (32 * MPW)        // 4352 words per row-slot
#define WP_STRIDE 33     // words per o-row of packed weights (aliased into ring)
#define ZSL 68           // words per o-row of a z slot (64 px-pairs + 4 pad)
#define RINGSLOT (64 * ZSL)      // 4352 words per z row-slot

// dynamic smem layout (bytes):
//   Mp    uint32_t[4][32*136] @ 0       (69632)  fp16x2 vertically-summed x rows (2 bufs x 2 rows)
//   ring  uint32_t[2][64*68]  @ 69632   (34816)  fp16x2 z rows (same-iteration produce/consume)
//         (Wp aliases ring start during phase 0 only)
//   BiasS float[64]           @ 104448  (256)
#define SMEM_BYTES 104704

static __device__ __forceinline__ float2 h2f(uint32_t w) {
    return __half22float2(*reinterpret_cast<__half2*>(&w));
}
static __device__ __forceinline__ uint32_t hadd2u(uint32_t a, uint32_t b) {
    __half2 r = __hadd2(*reinterpret_cast<__half2*>(&a), *reinterpret_cast<__half2*>(&b));
    return *reinterpret_cast<uint32_t*>(&r);
}
// convert one row's float4 pair-loads (2 groups x 2 channels) to 8 fp16x2 words
static __device__ __forceinline__ void cvt_row(const float4* xa, const float4* xc, uint32_t* c) {
    #pragma unroll
    for (int g = 0; g < 2; g++) {
        __half2 p0 = __floats2half2_rn(xa[g].x, xc[g].x);
        __half2 p1 = __floats2half2_rn(xa[g].y, xc[g].y);
        __half2 p2 = __floats2half2_rn(xa[g].z, xc[g].z);
        __half2 p3 = __floats2half2_rn(xa[g].w, xc[g].w);
        c[4 * g + 0] = *reinterpret_cast<uint32_t*>(&p0);
        c[4 * g + 1] = *reinterpret_cast<uint32_t*>(&p1);
        c[4 * g + 2] = *reinterpret_cast<uint32_t*>(&p2);
        c[4 * g + 3] = *reinterpret_cast<uint32_t*>(&p3);
    }
}

__global__ __launch_bounds__(512, 1)
void denoise_fused(const float* __restrict__ x,
                   const float* __restrict__ conv_w,
                   const float* __restrict__ conv_b,
                   float* __restrict__ out) {
    extern __shared__ unsigned char smraw[];
    uint32_t* Mp    = reinterpret_cast<uint32_t*>(smraw);
    uint32_t* ring  = reinterpret_cast<uint32_t*>(smraw + 69632);
    uint32_t* Wp    = ring;                       // alias, consumed before ring use
    float*    BiasS = reinterpret_cast<float*>(smraw + 104448);

    const int tid  = threadIdx.x;
    const int warp = tid >> 5;
    const int lane = tid & 31;

    const int b  = blockIdx.y;
    const int h0 = blockIdx.x * RROWS;

    // ---------- phase 0: stage weights fp16x2 + bias ----------
    for (int i = tid; i < 64 * 32; i += 512) {
        const int o = i >> 5, c2 = i & 31;
        const float2 wv = reinterpret_cast<const float2*>(conv_w)[o * 32 + c2];
        __half2 pk = __floats2half2_rn(wv.x, wv.y);
        Wp[o * WP_STRIDE + c2] = *reinterpret_cast<uint32_t*>(&pk);
    }
    if (tid < 64) BiasS[tid] = conv_b[tid];
    __syncthreads();

    // GEMM tiling: warps 0-7 -> row 0 of pair, 8-15 -> row 1.
    // Within 8 warps: 2 M-groups x 4 N-slices; 2 MMAs per B-fragment load.
    const int wrow = warp >> 3;
    const int wr   = warp & 7;
    const int o0   = (wr & 1) * 32;
    const int nsub = (wr >> 1) * 32;
    const int lq = lane >> 2;   // 0..7
    const int lr = lane & 3;    // 0..3

    uint32_t a[2][4][4];
    #pragma unroll
    for (int mt = 0; mt < 2; mt++) {
        const int ot = o0 + mt * 16;
        #pragma unroll
        for (int kk = 0; kk < 4; kk++) {
            a[mt][kk][0] = Wp[(ot + lq)     * WP_STRIDE + kk * 8 + lr];
            a[mt][kk][1] = Wp[(ot + 8 + lq) * WP_STRIDE + kk * 8 + lr];
            a[mt][kk][2] = Wp[(ot + lq)     * WP_STRIDE + kk * 8 + 4 + lr];
            a[mt][kk][3] = Wp[(ot + 8 + lq) * WP_STRIDE + kk * 8 + 4 + lr];
        }
    }

    const float* xb = x   + (size_t)b * CH * HW;
    float*       ob = out + (size_t)b * CH * HW;

    // per-thread load coords: channel pair c2p, two 4-px groups (pxp, pxp+64)
    const int c2p = tid >> 4;           // 0..31
    const int pxp = (tid & 15) * 4;     // 0..60
    const float* base0 = xb + (size_t)(2 * c2p)     * HW;
    const float* base1 = xb + (size_t)(2 * c2p + 1) * HW;

    // ---------- prologue: rolling vertical window ----------
    uint32_t xprev[8], sprev[8];
    {
        uint32_t xm1[8] = {0u,0u,0u,0u,0u,0u,0u,0u};
        float4 la[2], lc[2];
        if (h0 > 0) {
            #pragma unroll
            for (int g = 0; g < 2; g++) {
                la[g] = *reinterpret_cast<const float4*>(base0 + (h0 - 1) * WW + pxp + 64 * g);
                lc[g] = *reinterpret_cast<const float4*>(base1 + (h0 - 1) * WW + pxp + 64 * g);
            }
            cvt_row(la, lc, xm1);
        }
        #pragma unroll
        for (int g = 0; g < 2; g++) {
            la[g] = *reinterpret_cast<const float4*>(base0 + h0 * WW + pxp + 64 * g);
            lc[g] = *reinterpret_cast<const float4*>(base1 + h0 * WW + pxp + 64 * g);
        }
        uint32_t x0[8];
        cvt_row(la, lc, x0);
        #pragma unroll
        for (int j = 0; j < 8; j++) {
            sprev[j] = hadd2u(xm1[j], x0[j]);
            xprev[j] = x0[j];
        }
    }
    // prefetch rows h0+1, h0+2 (always in-bounds: h0 <= 120)
    float4 pa[2][2], pc[2][2];
    #pragma unroll
    for (int k = 0; k < 2; k++) {
        const int rr = h0 + 1 + k;
        #pragma unroll
        for (int g = 0; g < 2; g++) {
            pa[k][g] = *reinterpret_cast<const float4*>(base0 + rr * WW + pxp + 64 * g);
            pc[k][g] = *reinterpret_cast<const float4*>(base1 + rr * WW + pxp + 64 * g);
        }
    }

    // ---------- pipeline: 4 iterations, 2 output rows each ----------
    #pragma unroll 1
    for (int i = 0; i < 4; i++) {
        const int ro0 = h0 + 2 * i;
        uint32_t* mpb = Mp + (i & 1) * (2 * MPSLOT);

        // convert incoming rows ro0+1 (always valid), ro0+2 (guard)
        uint32_t c1[8], c2r[8] = {0u,0u,0u,0u,0u,0u,0u,0u};
        cvt_row(pa[0], pc[0], c1);
        if (ro0 + 2 < HH) cvt_row(pa[1], pc[1], c2r);

        // vertical 3-sums -> Mp (fp16x2)
        {
            uint32_t xv0[8], xv1[8];
            #pragma unroll
            for (int j = 0; j < 8; j++) {
                xv0[j] = hadd2u(sprev[j], c1[j]);
                xv1[j] = hadd2u(hadd2u(xprev[j], c1[j]), c2r[j]);
                sprev[j] = hadd2u(c1[j], c2r[j]);
                xprev[j] = c2r[j];
            }
            #pragma unroll
            for (int g = 0; g < 2; g++) {
                *reinterpret_cast<uint4*>(&mpb[c2p * MPW + pxp + 64 * g]) =
                    *reinterpret_cast<uint4*>(&xv0[4 * g]);
                *reinterpret_cast<uint4*>(&mpb[MPSLOT + c2p * MPW + pxp + 64 * g]) =
                    *reinterpret_cast<uint4*>(&xv1[4 * g]);
            }
        }

        // prefetch rows ro0+3, ro0+4 for next iteration (guard < HH)
        if (i < 3) {
            #pragma unroll
            for (int k = 0; k < 2; k++) {
                const int rr = ro0 + 3 + k;
                if (rr < HH) {
                    #pragma unroll
                    for (int g = 0; g < 2; g++) {
                        pa[k][g] = *reinterpret_cast<const float4*>(base0 + rr * WW + pxp + 64 * g);
                        pc[k][g] = *reinterpret_cast<const float4*>(base1 + rr * WW + pxp + 64 * g);
                    }
                }
            }
        }
        __syncthreads();   // Mp pair ready; ring slots free (prev epilogue done)

        // -- GEMM: z[o,p] = sum_c W[o,c] * xv[c,p] for row pair --
        {
            const uint32_t* mp = mpb + wrow * MPSLOT;
            uint32_t* zs = ring + wrow * RINGSLOT;
            #pragma unroll
            for (int nt = 0; nt < 4; nt++) {
                const int n0 = nsub + nt * 8;
                float ac[2][4];
                #pragma unroll
                for (int mt = 0; mt < 2; mt++)
                    ac[mt][0] = ac[mt][1] = ac[mt][2] = ac[mt][3] = 0.f;
                #pragma unroll
                for (int kk = 0; kk < 4; kk++) {
                    const uint32_t b0 = mp[(kk * 8 + lr)     * MPW + n0 + lq];
                    const uint32_t b1 = mp[(kk * 8 + 4 + lr) * MPW + n0 + lq];
                    #pragma unroll
                    for (int mt = 0; mt < 2; mt++) {
                        asm volatile(
                            "mma.sync.aligned.m16n8k16.row.col.f32.f16.f16.f32 "
                            "{%0,%1,%2,%3}, {%4,%5,%6,%7}, {%8,%9}, {%0,%1,%2,%3};\n"
                            : "+f"(ac[mt][0]), "+f"(ac[mt][1]),
                              "+f"(ac[mt][2]), "+f"(ac[mt][3])
                            : "r"(a[mt][kk][0]), "r"(a[mt][kk][1]),
                              "r"(a[mt][kk][2]), "r"(a[mt][kk][3]),
                              "r"(b0), "r"(b1));
                    }
                }
                #pragma unroll
                for (int mt = 0; mt < 2; mt++) {
                    const int oA = o0 + mt * 16 + lq;
                    __half2 d01 = __floats2half2_rn(ac[mt][0], ac[mt][1]);
                    __half2 d23 = __floats2half2_rn(ac[mt][2], ac[mt][3]);
                    zs[oA       * ZSL + (n0 >> 1) + lr] = *reinterpret_cast<uint32_t*>(&d01);
                    zs[(oA + 8) * ZSL + (n0 >> 1) + lr] = *reinterpret_cast<uint32_t*>(&d23);
                }
            }
        }
        __syncthreads();   // z pair ready

        // -- epilogue: horizontal 3-sum + scale + residual + bias, rows ro0, ro0+1 --
        #pragma unroll
        for (int it = 0; it < 4; it++) {
            const int idx  = it * 512 + tid;
            const int o    = idx >> 5;          // out channel 0..63
            const int rowk = (idx >> 4) & 1;    // == (tid>>4)&1
            const int q4   = idx & 15;          // uint4 group (8 px); == tid&15
            const int ro   = ro0 + rowk;

            const uint32_t* zv = ring + rowk * RINGSLOT;
            const int wb = o * ZSL + q4 * 4;

            const uint4 m4 = *reinterpret_cast<const uint4*>(&zv[wb]);
            float v[8];
            {
                float2 m;
                m = h2f(m4.x); v[0] = m.x; v[1] = m.y;
                m = h2f(m4.y); v[2] = m.x; v[3] = m.y;
                m = h2f(m4.z); v[4] = m.x; v[5] = m.y;
                m = h2f(m4.w); v[6] = m.x; v[7] = m.y;
            }
            // boundary values via neighbor lanes (cross-half at lane 15<->16
            // discarded by the q4 edge guards)
            const float vls = __shfl_sync(0xffffffffu, v[7], (lane - 1) & 31);
            const float vrs = __shfl_sync(0xffffffffu, v[0], (lane + 1) & 31);
            const float vl = (q4 == 0)  ? 0.f : vls;
            const float vr = (q4 == 15) ? 0.f : vrs;

            const float invh = (ro == 0 || ro == HH - 1) ? 0.5f : (1.0f / 3.0f);
            const int px0 = q4 * 8;
            const size_t off = (size_t)o * HW + ro * WW + px0;
            const float4 x0 = *reinterpret_cast<const float4*>(xb + off);
            const float4 x1 = *reinterpret_cast<const float4*>(xb + off + 4);
            const float bo = BiasS[o];
            const float iw  = (1.0f / 3.0f) * invh;
            const float iwL = (q4 == 0)  ? 0.5f * invh : iw;
            const float iwR = (q4 == 15) ? 0.5f * invh : iw;

            float4 o0v, o1v;
            o0v.x = x0.x + bo + (vl   + v[0] + v[1]) * iwL;
            o0v.y = x0.y + bo + (v[0] + v[1] + v[2]) * iw;
            o0v.z = x0.z + bo + (v[1] + v[2] + v[3]) * iw;
            o0v.w = x0.w + bo + (v[2] + v[3] + v[4]) * iw;
            o1v.x = x1.x + bo + (v[3] + v[4] + v[5]) * iw;
            o1v.y = x1.y + bo + (v[4] + v[5] + v[6]) * iw;
            o1v.z = x1.z + bo + (v[5] + v[6] + v[7]) * iw;
            o1v.w = x1.w + bo + (v[6] + v[7] + vr  ) * iwR;
            __stcs(reinterpret_cast<float4*>(ob + off), o0v);
            __stcs(reinterpret_cast<float4*>(ob + off + 4), o1v);
        }
        // next iteration's first barrier fences ring reuse
    }
}

extern "C" void kernel_launch(void* const* d_in, const int* in_sizes, int n_in,
                              void* d_out, int out_size) {
    const float* x      = (const float*)d_in[0];
    const float* conv_w = (const float*)d_in[1];
    const float* conv_b = (const float*)d_in[2];
    float* out = (float*)d_out;

    cudaFuncSetAttribute(denoise_fused,
                         cudaFuncAttributeMaxDynamicSharedMemorySize, SMEM_BYTES);
    dim3 grid(HH / RROWS, BZ);               // 16 x 32 = 512 CTAs
    denoise_fused<<<grid, 512, SMEM_BYTES>>>(x, conv_w, conv_b, out);
}